// round 16
// baseline (speedup 1.0000x reference)
#include <cuda_runtime.h>
#include <cuda_fp16.h>
#include <stdint.h>
#include <math.h>

#define N_NODES 100000
#define N_EDGES 1600000
#define HALF_E  (N_EDGES / 2)
#define FULL 0xffffffffu

// ---------------- scratch (static device globals; no allocations) ----------
// Edge record: {src | j<<20, dst, half2(b_j, b_j5), half2(b_j1, b_j6)}
__device__ int4   g_edge[N_EDGES];
__device__ float  g_deg[N_NODES];
__device__ float4 g_agg[N_NODES * 4];            // zero at call entry/exit
__device__ float4 g_h1[N_NODES * 4];
__device__ float4 g_h2[N_NODES * 4];
__device__ uint2  g_xwh[N_NODES * 100];          // [N][25][16] fp16 XW (80MB)

// ---------------- helpers ---------------------------------------------------

__device__ __forceinline__ void red_add_v4(float* p, float4 v) {
    asm volatile("red.global.add.v4.f32 [%0], {%1,%2,%3,%4};"
                 :: "l"(p), "f"(v.x), "f"(v.y), "f"(v.z), "f"(v.w) : "memory");
}

__device__ __forceinline__ float2 h2f2(unsigned u) {
    __half2 h = *reinterpret_cast<__half2*>(&u);
    return __half22float2(h);
}

__device__ __forceinline__ unsigned packh2(float a, float b) {
    __half2 h = __floats2half2_rn(a, b);
    return *reinterpret_cast<unsigned*>(&h);
}

// ---------------- kernels --------------------------------------------------

__global__ void zero_deg_kernel() {
    int i = blockIdx.x * blockDim.x + threadIdx.x;
    if (i < N_NODES) g_deg[i] = 0.f;
}

// Fused prep + layer-1 edge kernel. 4 threads/edge, 2 edges/thread.
__global__ void prep_edge1_kernel(const float2* __restrict__ attr,
                                  const int* __restrict__ src,
                                  const int* __restrict__ dst,
                                  const float2* __restrict__ x,
                                  const float* __restrict__ W1) {
    __shared__ uint4 Wsh[100];                   // [25][4] fp16
    if (threadIdx.x < 100) {
        int w = threadIdx.x >> 2, l = threadIdx.x & 3;
        const float4* Wv = (const float4*)W1;    // [25][2][4] float4
        float4 a0 = Wv[w * 8 + l];
        float4 a1 = Wv[w * 8 + 4 + l];
        uint4 u;
        u.x = packh2(a0.x, a0.y);
        u.y = packh2(a0.z, a0.w);
        u.z = packh2(a1.x, a1.y);
        u.w = packh2(a1.z, a1.w);
        Wsh[w * 4 + l] = u;
    }
    __syncthreads();
    int t = blockIdx.x * blockDim.x + threadIdx.x;
    int l = threadIdx.x & 3;
    const int woff[4] = {0, 5, 1, 6};
#pragma unroll
    for (int half = 0; half < 2; half++) {
        int e = (t >> 2) + half * HALF_E;
        float2 a = __ldcs(&attr[e]);
        int s = __ldcs(&src[e]);
        int d = __ldcs(&dst[e]);
        float v0 = a.x * 4.f, v1 = a.y * 4.f;
        float k0f = fminf(fmaxf(floorf(v0), 0.f), 3.f);
        float k1f = fminf(fmaxf(floorf(v1), 0.f), 3.f);
        float f0 = v0 - k0f, f1 = v1 - k1f;
        int j = (int)k0f + 5 * (int)k1f;
        float bj  = (1.f - f0) * (1.f - f1);
        float bj5 = (1.f - f0) * f1;
        float bj1 = f0 * (1.f - f1);
        float bj6 = f0 * f1;
        int rx = s | (j << 20);
        int rz = (int)packh2(bj,  bj5);
        int rw = (int)packh2(bj1, bj6);
        int comp = (l == 0) ? rx : (l == 1) ? d : (l == 2) ? rz : rw;
        __stcs(&((int*)g_edge)[(size_t)e * 4 + l], comp);
        if (l == 0) atomicAdd(&g_deg[d], 1.f);
        float2 xv = x[s];
        float bs[4] = {bj, bj5, bj1, bj6};
        float4 acc = make_float4(0.f, 0.f, 0.f, 0.f);
#pragma unroll
        for (int q = 0; q < 4; q++) {
            uint4 wv = Wsh[(j + woff[q]) * 4 + l];
            float2 w00 = h2f2(wv.x), w01 = h2f2(wv.y);
            float2 w10 = h2f2(wv.z), w11 = h2f2(wv.w);
            float c0 = bs[q] * xv.x, c1 = bs[q] * xv.y;
            acc.x += c0 * w00.x + c1 * w10.x;
            acc.y += c0 * w00.y + c1 * w10.y;
            acc.z += c0 * w01.x + c1 * w11.x;
            acc.w += c0 * w01.y + c1 * w11.y;
        }
        red_add_v4((float*)&g_agg[(size_t)d * 4 + l], acc);
    }
}

// XW via warp-level mma.sync (m16n8k16, fp16 in, fp32 accum).
// Block = 256 threads / 8 warps / 128 nodes. B fragments for the whole
// [16 x 400] W matrix staged once per block; warp w owns nodes n0+16w..+15.
// D tile (16x8): thread's c0/c1 are adjacent cols of row g, c2/c3 of row g+8
// -> direct half2 stores to g_xwh, no shuffle.
__global__ void xw_hmma_kernel(const float4* __restrict__ hin,
                               const float* __restrict__ W) {
    __shared__ unsigned bfrag[50 * 64];          // [tile][lane][2]
    __shared__ unsigned ha[128 * 8];             // fp16 h rows (8 half2 per node)
    int tid = threadIdx.x;
    int n0 = blockIdx.x * 128;
    // B fragments: entry pair (t, l): col = t*8 + g; k rows (2tig,2tig+1)/(+8,+9)
    for (int idx = tid; idx < 1600; idx += 256) {
        int t = idx >> 5, l = idx & 31;
        int g = l >> 2, tig = l & 3;
        int col = t * 8 + g;
        const float* wp = W + (col >> 4) * 256 + (col & 15);   // W[kk][i][ch], stride 16 per i
        bfrag[idx * 2]     = packh2(wp[(2 * tig) * 16],     wp[(2 * tig + 1) * 16]);
        bfrag[idx * 2 + 1] = packh2(wp[(2 * tig + 8) * 16], wp[(2 * tig + 9) * 16]);
    }
    // A rows: 2 threads per node, each converts 8 floats -> 4 half2
    {
        int r = tid >> 1, hf = tid & 1;
        int n = n0 + r; if (n >= N_NODES) n = N_NODES - 1;
        const float4* hp = hin + (size_t)n * 4 + hf * 2;
        float4 v0 = hp[0], v1 = hp[1];
        unsigned* dst = &ha[r * 8 + hf * 4];
        dst[0] = packh2(v0.x, v0.y);
        dst[1] = packh2(v0.z, v0.w);
        dst[2] = packh2(v1.x, v1.y);
        dst[3] = packh2(v1.z, v1.w);
    }
    __syncthreads();
    int warp = tid >> 5, lane = tid & 31;
    int g = lane >> 2, tig = lane & 3;
    int rb = warp * 16;
    unsigned a0 = ha[(rb + g) * 8 + tig];
    unsigned a1 = ha[(rb + g + 8) * 8 + tig];
    unsigned a2 = ha[(rb + g) * 8 + tig + 4];
    unsigned a3 = ha[(rb + g + 8) * 8 + tig + 4];
    int nA = n0 + rb + g, nB = nA + 8;
    bool wA = nA < N_NODES, wB = nB < N_NODES;
    unsigned* xw_u = (unsigned*)g_xwh;           // 200 half2 per node
    size_t baseA = (size_t)nA * 200 + tig;
    size_t baseB = (size_t)nB * 200 + tig;
#pragma unroll 2
    for (int t = 0; t < 50; t++) {
        unsigned b0 = bfrag[t * 64 + lane * 2];
        unsigned b1 = bfrag[t * 64 + lane * 2 + 1];
        float d0, d1, d2, d3;
        asm volatile(
            "mma.sync.aligned.m16n8k16.row.col.f32.f16.f16.f32 "
            "{%0,%1,%2,%3}, {%4,%5,%6,%7}, {%8,%9}, {%10,%11,%12,%13};"
            : "=f"(d0), "=f"(d1), "=f"(d2), "=f"(d3)
            : "r"(a0), "r"(a1), "r"(a2), "r"(a3), "r"(b0), "r"(b1),
              "f"(0.f), "f"(0.f), "f"(0.f), "f"(0.f));
        unsigned o0 = packh2(d0, d1);
        unsigned o1 = packh2(d2, d3);
        if (wA) xw_u[baseA + t * 4] = o0;
        if (wB) xw_u[baseB + t * 4] = o1;
    }
}

// Edge gather for layers 2/3: 4 threads/edge, TWO edges per thread.
__global__ void edge_gather_kernel() {
    int t = blockIdx.x * blockDim.x + threadIdx.x;
    int eA = t >> 2;
    int eB = eA + HALF_E;
    int l = threadIdx.x & 3;
    int4 recA = __ldcs(&g_edge[eA]);
    int4 recB = __ldcs(&g_edge[eB]);
    int sA = recA.x & 0xFFFFF, jA = recA.x >> 20;
    int sB = recB.x & 0xFFFFF, jB = recB.x >> 20;
    const char* baseA = (const char*)g_xwh + (size_t)sA * 800 + l * 16;
    const char* baseB = (const char*)g_xwh + (size_t)sB * 800 + l * 16;
    uint4 vA1 = *reinterpret_cast<const uint4*>(baseA + jA * 32);
    uint4 vA2 = *reinterpret_cast<const uint4*>(baseA + (jA + 5) * 32);
    uint4 vB1 = *reinterpret_cast<const uint4*>(baseB + jB * 32);
    uint4 vB2 = *reinterpret_cast<const uint4*>(baseB + (jB + 5) * 32);
    {
        float2 b0 = h2f2(recA.z), b1 = h2f2(recA.w);
        float cA = (l & 2) ? b1.x : b0.x;
        float cB = (l & 2) ? b1.y : b0.y;
        float acc[8];
        const unsigned* u1 = reinterpret_cast<const unsigned*>(&vA1);
        const unsigned* u2 = reinterpret_cast<const unsigned*>(&vA2);
#pragma unroll
        for (int i = 0; i < 4; i++) {
            float2 f1 = h2f2(u1[i]);
            float2 f2 = h2f2(u2[i]);
            acc[2 * i]     = cA * f1.x + cB * f2.x;
            acc[2 * i + 1] = cA * f1.y + cB * f2.y;
        }
#pragma unroll
        for (int i = 0; i < 8; i++)
            acc[i] += __shfl_xor_sync(FULL, acc[i], 2);
        float* ap = (float*)g_agg + (size_t)recA.y * 16 + ((l & 1) << 3) + ((l & 2) << 1);
        float4 out = (l & 2) ? make_float4(acc[4], acc[5], acc[6], acc[7])
                             : make_float4(acc[0], acc[1], acc[2], acc[3]);
        red_add_v4(ap, out);
    }
    {
        float2 b0 = h2f2(recB.z), b1 = h2f2(recB.w);
        float cA = (l & 2) ? b1.x : b0.x;
        float cB = (l & 2) ? b1.y : b0.y;
        float acc[8];
        const unsigned* u1 = reinterpret_cast<const unsigned*>(&vB1);
        const unsigned* u2 = reinterpret_cast<const unsigned*>(&vB2);
#pragma unroll
        for (int i = 0; i < 4; i++) {
            float2 f1 = h2f2(u1[i]);
            float2 f2 = h2f2(u2[i]);
            acc[2 * i]     = cA * f1.x + cB * f2.x;
            acc[2 * i + 1] = cA * f1.y + cB * f2.y;
        }
#pragma unroll
        for (int i = 0; i < 8; i++)
            acc[i] += __shfl_xor_sync(FULL, acc[i], 2);
        float* ap = (float*)g_agg + (size_t)recB.y * 16 + ((l & 1) << 3) + ((l & 2) << 1);
        float4 out = (l & 2) ? make_float4(acc[4], acc[5], acc[6], acc[7])
                             : make_float4(acc[0], acc[1], acc[2], acc[3]);
        red_add_v4(ap, out);
    }
}

// Node update, layer 1.
__global__ void node1_kernel(const float2* __restrict__ x,
                             const float* __restrict__ root,
                             const float* __restrict__ bias,
                             float4* __restrict__ hout) {
    __shared__ float4 rsh[8];
    __shared__ float4 bsh[4];
    if (threadIdx.x < 8)  rsh[threadIdx.x] = ((const float4*)root)[threadIdx.x];
    if (threadIdx.x < 4)  bsh[threadIdx.x] = ((const float4*)bias)[threadIdx.x];
    __syncthreads();
    int t = blockIdx.x * blockDim.x + threadIdx.x;
    int n = t >> 2;
    if (n >= N_NODES) return;
    int l = t & 3;
    float4 a = g_agg[(size_t)n * 4 + l];
    float di = 1.f / fmaxf(g_deg[n], 1.f);
    float2 xv = x[n];
    float4 r0 = rsh[l], r1 = rsh[4 + l], bb = bsh[l];
    float4 o;
    o.x = fmaxf(bb.x + a.x * di + xv.x * r0.x + xv.y * r1.x, 0.f);
    o.y = fmaxf(bb.y + a.y * di + xv.x * r0.y + xv.y * r1.y, 0.f);
    o.z = fmaxf(bb.z + a.z * di + xv.x * r0.z + xv.y * r1.z, 0.f);
    o.w = fmaxf(bb.w + a.w * di + xv.x * r0.w + xv.y * r1.w, 0.f);
    hout[(size_t)n * 4 + l] = o;
    g_agg[(size_t)n * 4 + l] = make_float4(0.f, 0.f, 0.f, 0.f);
}

// Node update, 16-channel root.
__global__ void node16_kernel(const float4* __restrict__ hin,
                              const float* __restrict__ root,
                              const float* __restrict__ bias,
                              float4* __restrict__ hout) {
    __shared__ float4 rsh[64];
    __shared__ float4 bsh[4];
    for (int j = threadIdx.x; j < 64; j += blockDim.x)
        rsh[j] = ((const float4*)root)[j];
    if (threadIdx.x < 4) bsh[threadIdx.x] = ((const float4*)bias)[threadIdx.x];
    __syncthreads();
    int t = blockIdx.x * blockDim.x + threadIdx.x;
    int n = t >> 2;
    if (n >= N_NODES) return;
    int l = t & 3;
    float4 a = g_agg[(size_t)n * 4 + l];
    float di = 1.f / fmaxf(g_deg[n], 1.f);
    float4 acc = bsh[l];
    acc.x += a.x * di; acc.y += a.y * di; acc.z += a.z * di; acc.w += a.w * di;
    const float* h = (const float*)(hin + (size_t)n * 4);
#pragma unroll
    for (int i = 0; i < 16; i++) {
        float hv = h[i];
        float4 r = rsh[i * 4 + l];
        acc.x += hv * r.x; acc.y += hv * r.y; acc.z += hv * r.z; acc.w += hv * r.w;
    }
    acc.x = fmaxf(acc.x, 0.f); acc.y = fmaxf(acc.y, 0.f);
    acc.z = fmaxf(acc.z, 0.f); acc.w = fmaxf(acc.w, 0.f);
    hout[(size_t)n * 4 + l] = acc;
    g_agg[(size_t)n * 4 + l] = make_float4(0.f, 0.f, 0.f, 0.f);
}

// Layer-3 node update fused with fc head.
__global__ void node16_final_kernel(const float4* __restrict__ hin,
                                    const float* __restrict__ root,
                                    const float* __restrict__ bias,
                                    const float* __restrict__ fcw,
                                    const float* __restrict__ fcb,
                                    float* __restrict__ out) {
    __shared__ float4 rsh[64];
    __shared__ float4 bsh[4];
    __shared__ float4 wsh[4];
    for (int j = threadIdx.x; j < 64; j += blockDim.x)
        rsh[j] = ((const float4*)root)[j];
    if (threadIdx.x < 4) {
        bsh[threadIdx.x] = ((const float4*)bias)[threadIdx.x];
        wsh[threadIdx.x] = ((const float4*)fcw)[threadIdx.x];
    }
    __syncthreads();
    int t = blockIdx.x * blockDim.x + threadIdx.x;
    int n = t >> 2;
    if (n >= N_NODES) return;
    int l = t & 3;
    float4 a = g_agg[(size_t)n * 4 + l];
    float di = 1.f / fmaxf(g_deg[n], 1.f);
    float4 acc = bsh[l];
    acc.x += a.x * di; acc.y += a.y * di; acc.z += a.z * di; acc.w += a.w * di;
    const float* h = (const float*)(hin + (size_t)n * 4);
#pragma unroll
    for (int i = 0; i < 16; i++) {
        float hv = h[i];
        float4 r = rsh[i * 4 + l];
        acc.x += hv * r.x; acc.y += hv * r.y; acc.z += hv * r.z; acc.w += hv * r.w;
    }
    acc.x = fmaxf(acc.x, 0.f); acc.y = fmaxf(acc.y, 0.f);
    acc.z = fmaxf(acc.z, 0.f); acc.w = fmaxf(acc.w, 0.f);
    g_agg[(size_t)n * 4 + l] = make_float4(0.f, 0.f, 0.f, 0.f);
    float4 wv = wsh[l];
    float z = acc.x * wv.x + acc.y * wv.y + acc.z * wv.z + acc.w * wv.w;
    z += __shfl_xor_sync(FULL, z, 1);
    z += __shfl_xor_sync(FULL, z, 2);
    if (l == 0) out[n] = 1.f / (1.f + expf(-(z + fcb[0])));
}

// ---------------- launch ---------------------------------------------------

extern "C" void kernel_launch(void* const* d_in, const int* in_sizes, int n_in,
                              void* d_out, int out_size) {
    const float2* x     = (const float2*)d_in[0];
    const int*    ei    = (const int*)d_in[1];
    const float2* attr  = (const float2*)d_in[2];
    const float*  W1    = (const float*)d_in[3];
    const float*  root1 = (const float*)d_in[4];
    const float*  b1    = (const float*)d_in[5];
    const float*  W2    = (const float*)d_in[6];
    const float*  root2 = (const float*)d_in[7];
    const float*  b2    = (const float*)d_in[8];
    const float*  W3    = (const float*)d_in[9];
    const float*  root3 = (const float*)d_in[10];
    const float*  b3    = (const float*)d_in[11];
    const float*  fcw   = (const float*)d_in[12];
    const float*  fcb   = (const float*)d_in[13];
    const int* src = ei;
    const int* dst = ei + N_EDGES;

    float4 *h1, *h2;
    cudaGetSymbolAddress((void**)&h1, g_h1);
    cudaGetSymbolAddress((void**)&h2, g_h2);

    const int TB = 256;
    int gEdge2 = (HALF_E * 4) / TB;              // 12500
    int gNode4 = (N_NODES * 4 + TB - 1) / TB;
    int gNode  = (N_NODES + TB - 1) / TB;
    int gXW    = (N_NODES + 127) / 128;          // 782

    zero_deg_kernel<<<gNode, TB>>>();

    // fused: prep + layer-1 edge phase
    prep_edge1_kernel<<<gEdge2, TB>>>(attr, src, dst, x, W1);
    node1_kernel<<<gNode4, TB>>>(x, root1, b1, h1);

    // layer 2
    xw_hmma_kernel<<<gXW, 256>>>(h1, W2);
    edge_gather_kernel<<<gEdge2, TB>>>();
    node16_kernel<<<gNode4, TB>>>(h1, root2, b2, h2);

    // layer 3
    xw_hmma_kernel<<<gXW, 256>>>(h2, W3);
    edge_gather_kernel<<<gEdge2, TB>>>();
    node16_final_kernel<<<gNode4, TB>>>(h2, root3, b3, fcw, fcb, (float*)d_out);
}